// round 16
// baseline (speedup 1.0000x reference)
#include <cuda_runtime.h>
#include <cuda_bf16.h>
#include <math.h>

#define B_DIM 32
#define H_DIM 56
#define W_DIM 56
#define C_DIM 256
#define HW (H_DIM * W_DIM)             // 3136
#define NPIX (B_DIM * HW)              // 100352
#define NROWS (B_DIM * H_DIM)          // 1792 CS rows

#define PPB 32                         // pixels per pool item
#define NPOOL (NPIX / PPB)             // 3136 pool items
#define GROUP 11                       // 7 pool + 4 cs slots per group
#define LAG_G 100                      // cs delayed by 100 groups
#define TOT_G (NPOOL / 7 + LAG_G)      // 548 groups
#define GRID_BLKS (TOT_G * GROUP)      // 6028

// Scratch (no cudaMalloc allowed).
__device__ float2 g_pooled[NPIX];
__device__ int    g_pool_done[NPOOL];

__global__ void reset_kernel() {
    int i = blockIdx.x * blockDim.x + threadIdx.x;
    if (i < NPOOL) g_pool_done[i] = 0;
}

struct f8 { float4 a, b; };
__device__ __forceinline__ f8 ldg_f8(const float* p) {
    f8 r;
    unsigned long long d0, d1, d2, d3;
    asm volatile("ld.global.v4.b64 {%0,%1,%2,%3}, [%4];"
                 : "=l"(d0), "=l"(d1), "=l"(d2), "=l"(d3)
                 : "l"(p));
    r.a.x = __uint_as_float((unsigned)(d0));
    r.a.y = __uint_as_float((unsigned)(d0 >> 32));
    r.a.z = __uint_as_float((unsigned)(d1));
    r.a.w = __uint_as_float((unsigned)(d1 >> 32));
    r.b.x = __uint_as_float((unsigned)(d2));
    r.b.y = __uint_as_float((unsigned)(d2 >> 32));
    r.b.z = __uint_as_float((unsigned)(d3));
    r.b.w = __uint_as_float((unsigned)(d3 >> 32));
    return r;
}

// ---------------------------------------------------------------------------
// One launch; role chosen by blockIdx. Group of 11 consecutive blocks:
//   slot 0..6  -> pool item p = g*7+slot   (32 pixels each)
//   slot 7..10 -> cs row j = (g-LAG_G)*4+(slot-7)
// CS blocks PREFETCH their first 7 float4 x-loads before the flag spin and
// conv: the loads are in flight while the conv computes, so the conv phase
// is hidden under memory latency instead of serializing before streaming.
// ---------------------------------------------------------------------------
__global__ void __launch_bounds__(256) mega_kernel(
    const float* __restrict__ x,
    const float* __restrict__ w,     // [7,7,2,1] HWIO
    const float* __restrict__ bias,  // [1]
    float* __restrict__ out)
{
    const int g    = blockIdx.x / GROUP;
    const int slot = blockIdx.x - g * GROUP;
    const int tid  = threadIdx.x;

    if (slot < 7) {
        // ======================= pool item =======================
        int p = g * 7 + slot;
        if (p >= NPOOL) return;

        const int wid  = tid >> 5;
        const int lane = tid & 31;
        const int sub  = lane >> 3;
        const int co   = lane & 7;
        int pix = p * PPB + wid * 4 + sub;

        const float* __restrict__ xr = x + (size_t)pix * C_DIM;
        f8 u0 = ldg_f8(xr + co * 8);
        f8 u1 = ldg_f8(xr + co * 8 + 64);
        f8 u2 = ldg_f8(xr + co * 8 + 128);
        f8 u3 = ldg_f8(xr + co * 8 + 192);

        float4 v0 = u0.a, v1 = u0.b, v2 = u1.a, v3 = u1.b;
        float4 v4 = u2.a, v5 = u2.b, v6 = u3.a, v7 = u3.b;

        float s = (((v0.x+v0.y)+(v0.z+v0.w)) + ((v1.x+v1.y)+(v1.z+v1.w)))
                + (((v2.x+v2.y)+(v2.z+v2.w)) + ((v3.x+v3.y)+(v3.z+v3.w)))
                + (((v4.x+v4.y)+(v4.z+v4.w)) + ((v5.x+v5.y)+(v5.z+v5.w)))
                + (((v6.x+v6.y)+(v6.z+v6.w)) + ((v7.x+v7.y)+(v7.z+v7.w)));

        float m01 = fmaxf(fmaxf(fmaxf(v0.x,v0.y), fmaxf(v0.z,v0.w)),
                          fmaxf(fmaxf(v1.x,v1.y), fmaxf(v1.z,v1.w)));
        float m23 = fmaxf(fmaxf(fmaxf(v2.x,v2.y), fmaxf(v2.z,v2.w)),
                          fmaxf(fmaxf(v3.x,v3.y), fmaxf(v3.z,v3.w)));
        float m45 = fmaxf(fmaxf(fmaxf(v4.x,v4.y), fmaxf(v4.z,v4.w)),
                          fmaxf(fmaxf(v5.x,v5.y), fmaxf(v5.z,v5.w)));
        float m67 = fmaxf(fmaxf(fmaxf(v6.x,v6.y), fmaxf(v6.z,v6.w)),
                          fmaxf(fmaxf(v7.x,v7.y), fmaxf(v7.z,v7.w)));
        float m = fmaxf(fmaxf(m01, m23), fmaxf(m45, m67));

        #pragma unroll
        for (int off = 4; off; off >>= 1) {
            s += __shfl_xor_sync(0xffffffffu, s, off);
            m = fmaxf(m, __shfl_xor_sync(0xffffffffu, m, off));
        }

        if (co == 0)
            g_pooled[pix] = make_float2(s * (1.0f / 256.0f), m);

        __syncthreads();
        if (tid == 0) {
            __threadfence();
            atomicExch(&g_pool_done[p], 1);
        }
    } else {
        // ================ conv + sigmoid + scale row ================
        if (g < LAG_G) return;
        int j = (g - LAG_G) * 4 + (slot - 7);
        if (j >= NROWS) return;

        __shared__ float attn_s[W_DIM];

        int img = j / H_DIM;
        int row = j - img * H_DIM;

        const size_t base = ((size_t)img * HW + (size_t)row * W_DIM) * (C_DIM / 4);
        const float4* __restrict__ xr = (const float4*)x;
        float4* __restrict__ o = (float4*)out;

        // ---- PREFETCH batch 1 (7 float4/thread) BEFORE spin + conv ----
        float4 v[7];
        #pragma unroll
        for (int jj = 0; jj < 7; jj++)
            v[jj] = __ldcs(&xr[base + tid + (size_t)jj * 256]);

        // pool items covering rows [row-3, row+3] of this image
        int pix_lo = (img * H_DIM + (row > 3 ? row - 3 : 0)) * W_DIM;
        int pix_hi = (img * H_DIM + (row + 3 < H_DIM ? row + 3 : H_DIM - 1)) * W_DIM
                     + W_DIM - 1;
        int p_lo = pix_lo / PPB;
        int p_hi = pix_hi / PPB;          // <= p_lo + 13

        if (tid <= p_hi - p_lo) {
            volatile int* f = &g_pool_done[p_lo + tid];
            while (*f == 0) { __nanosleep(64); }
        }
        __syncthreads();
        __threadfence();

        // conv (hidden under the in-flight prefetch loads)
        if (tid < W_DIM) {
            const float2* __restrict__ pooled_b = g_pooled + img * HW;
            float acc = __ldg(bias);
            #pragma unroll
            for (int dy = 0; dy < 7; dy++) {
                int gy = row + dy - 3;
                if (gy >= 0 && gy < H_DIM) {
                    const float2* __restrict__ prow = pooled_b + gy * W_DIM;
                    #pragma unroll
                    for (int dx = 0; dx < 7; dx++) {
                        int gx = tid + dx - 3;
                        if (gx >= 0 && gx < W_DIM) {
                            float2 p = __ldg(&prow[gx]);
                            acc = fmaf(p.x, __ldg(&w[(dy*7+dx)*2+0]), acc);
                            acc = fmaf(p.y, __ldg(&w[(dy*7+dx)*2+1]), acc);
                        }
                    }
                }
            }
            attn_s[tid] = 1.0f / (1.0f + __expf(-acc));
        }
        __syncthreads();

        // ---- consume batch 1; issue batch 2 loads before the stores ----
        float a1[7];
        #pragma unroll
        for (int jj = 0; jj < 7; jj++)
            a1[jj] = attn_s[(tid + jj * 256) >> 6];

        float4 v2[7];
        #pragma unroll
        for (int jj = 0; jj < 7; jj++)
            v2[jj] = __ldcs(&xr[base + tid + (size_t)(7 + jj) * 256]);

        #pragma unroll
        for (int jj = 0; jj < 7; jj++) {
            v[jj].x *= a1[jj]; v[jj].y *= a1[jj];
            v[jj].z *= a1[jj]; v[jj].w *= a1[jj];
        }
        #pragma unroll
        for (int jj = 0; jj < 7; jj++)
            __stcs(&o[base + tid + (size_t)jj * 256], v[jj]);

        // ---- batch 2 ----
        float a2[7];
        #pragma unroll
        for (int jj = 0; jj < 7; jj++)
            a2[jj] = attn_s[(tid + (7 + jj) * 256) >> 6];
        #pragma unroll
        for (int jj = 0; jj < 7; jj++) {
            v2[jj].x *= a2[jj]; v2[jj].y *= a2[jj];
            v2[jj].z *= a2[jj]; v2[jj].w *= a2[jj];
        }
        #pragma unroll
        for (int jj = 0; jj < 7; jj++)
            __stcs(&o[base + tid + (size_t)(7 + jj) * 256], v2[jj]);
    }
}

extern "C" void kernel_launch(void* const* d_in, const int* in_sizes, int n_in,
                              void* d_out, int out_size) {
    const float* x  = (const float*)d_in[0];
    const float* w  = (const float*)d_in[1];
    const float* b  = (const float*)d_in[2];
    float* out = (float*)d_out;

    reset_kernel<<<(NPOOL + 255) / 256, 256>>>();
    mega_kernel<<<GRID_BLKS, 256>>>(x, w, b, out);
}